// round 3
// baseline (speedup 1.0000x reference)
#include <cuda_runtime.h>
#include <math.h>

#define NB    64
#define NI    2048
#define KA    8
#define NO    32
#define OA    16
#define OUT   512

#define I_TILE 32
#define NWARP  16
#define NTHR   512

__device__ float g_S[NB * OUT];       // cumulative sum of activations
__device__ float g_preact[NB * OUT];

typedef unsigned long long u64;

// ---- f32x2 helpers ----
__device__ __forceinline__ u64 fma2(u64 a, u64 b, u64 c) {
    u64 d; asm("fma.rn.f32x2 %0, %1, %2, %3;" : "=l"(d) : "l"(a), "l"(b), "l"(c)); return d;
}
__device__ __forceinline__ u64 pack2(float lo, float hi) {
    u64 d; asm("mov.b64 %0, {%1, %2};" : "=l"(d) : "f"(lo), "f"(hi)); return d;
}
__device__ __forceinline__ void unpack2(u64 v, float& lo, float& hi) {
    asm("mov.b64 {%0, %1}, %2;" : "=f"(lo), "=f"(hi) : "l"(v));
}
__device__ __forceinline__ void cp16(void* smem_dst, const void* gsrc) {
    unsigned s = (unsigned)__cvta_generic_to_shared(smem_dst);
    asm volatile("cp.async.cg.shared.global [%0], [%1], 16;" :: "r"(s), "l"(gsrc));
}

// ---------------------------------------------------------------- zero
__global__ void k_zero() {
    int t = blockIdx.x * blockDim.x + threadIdx.x;
    if (t < NB * OUT) { g_S[t] = 0.0f; g_preact[t] = 0.0f; }
}

// ---------------------------------------------------------------- fused route
// grid = (NI/I_TILE=64, NB/32=2), block = 512 (16 warps).
// lane = b_local; warp w owns outputs [32w, 32w+32) = capsules {2w, 2w+1}.
// W slices are warp-private in smem (cp.async double buffer, warp-local sync).
// Softmax over 32 capsules: cross-warp exp-sum exchange via smem, 1 barrier/i.
template<bool PASS0>
__global__ void __launch_bounds__(NTHR, 1)
k_route(const float* __restrict__ x, const float* __restrict__ W) {
    __shared__ float ws[NWARP][2][KA][32];    // 32 KB: per-warp W slices, dbl-buffered
    __shared__ float part[2][NWARP][32];      // 4 KB: exp partial sums, dbl-buffered

    const int tid  = threadIdx.x;
    const int w    = tid >> 5;
    const int lane = tid & 31;
    const int it0  = blockIdx.x * I_TILE;
    const int b    = blockIdx.y * 32 + lane;
    const int out0 = w * 32;

    // S[b, out0..out0+31] in registers (16 u64 = atom pairs). Unused in pass 0.
    u64 s[16];
    if (!PASS0) {
        const ulonglong2* sp = reinterpret_cast<const ulonglong2*>(&g_S[(size_t)b * OUT + out0]);
#pragma unroll
        for (int q = 0; q < 8; q++) { ulonglong2 t = sp[q]; s[2*q] = t.x; s[2*q+1] = t.y; }
    }

    // Warp-private prefetch of W[i][k][out0..out0+31]: 64 chunks of 16B, 2 per lane.
    const float* Wg = W + out0;
#pragma unroll 1
    {
        const int c0 = lane, k0 = c0 >> 3, g0 = c0 & 7;
        const int c1 = lane + 32, k1 = c1 >> 3, g1 = c1 & 7;
        cp16(&ws[w][0][k0][g0 * 4], Wg + ((size_t)it0 * KA + k0) * OUT + g0 * 4);
        cp16(&ws[w][0][k1][g1 * 4], Wg + ((size_t)it0 * KA + k1) * OUT + g1 * 4);
        asm volatile("cp.async.commit_group;" ::: "memory");
    }

    u64 acc[16];
#pragma unroll
    for (int p = 0; p < 16; p++) acc[p] = 0ull;

    const int c0 = lane, k0 = c0 >> 3, g0 = c0 & 7;
    const int c1 = lane + 32, k1 = c1 >> 3, g1 = c1 & 7;

    for (int ii = 0; ii < I_TILE; ii++) {
        const int i = it0 + ii;

        if (ii + 1 < I_TILE) {       // prefetch next i into other buffer
            const int buf = (ii + 1) & 1;
            cp16(&ws[w][buf][k0][g0 * 4], Wg + ((size_t)(i + 1) * KA + k0) * OUT + g0 * 4);
            cp16(&ws[w][buf][k1][g1 * 4], Wg + ((size_t)(i + 1) * KA + k1) * OUT + g1 * 4);
            asm volatile("cp.async.commit_group;" ::: "memory");
            asm volatile("cp.async.wait_group 1;" ::: "memory");
        } else {
            asm volatile("cp.async.wait_group 0;" ::: "memory");
        }
        __syncwarp();

        // x[b, i, 0..8) — same address for all 16 warps -> L1 broadcast
        const float4* xp = reinterpret_cast<const float4*>(x + ((size_t)b * NI + i) * KA);
        float4 x0 = __ldg(xp), x1 = __ldg(xp + 1);
        float xk[KA] = {x0.x, x0.y, x0.z, x0.w, x1.x, x1.y, x1.z, x1.w};

        // votes for (b=lane, 32 outs) — W loads are warp-uniform broadcasts
        u64 v[16];
#pragma unroll
        for (int p = 0; p < 16; p++) v[p] = 0ull;
#pragma unroll
        for (int k = 0; k < KA; k++) {
            u64 xb = pack2(xk[k], xk[k]);
            const ulonglong2* wrow = reinterpret_cast<const ulonglong2*>(ws[w][ii & 1][k]);
#pragma unroll
            for (int q = 0; q < 8; q++) {
                ulonglong2 wv = wrow[q];
                v[2*q]   = fma2(xb, wv.x, v[2*q]);
                v[2*q+1] = fma2(xb, wv.y, v[2*q+1]);
            }
        }

        float r0, r1;
        if (PASS0) {
            r0 = r1 = 1.0f / 33.0f;          // softmax of zero logits (incl. leak)
        } else {
            u64 l0 = 0ull, l1 = 0ull;
#pragma unroll
            for (int p = 0; p < 8; p++) {
                l0 = fma2(v[p],     s[p],     l0);
                l1 = fma2(v[p + 8], s[p + 8], l1);
            }
            float a0, a1; unpack2(l0, a0, a1); float lg0 = a0 + a1;
            unpack2(l1, a0, a1);               float lg1 = a0 + a1;
            float e0 = __expf(lg0), e1 = __expf(lg1);

            part[ii & 1][w][lane] = e0 + e1;
            __syncthreads();
            float tot = 0.0f;
#pragma unroll
            for (int u = 0; u < NWARP; u++) tot += part[ii & 1][u][lane];
            float inv = __fdividef(1.0f, 1.0f + tot);   // leaky softmax (leak logit 0)
            r0 = e0 * inv; r1 = e1 * inv;
        }

        u64 ra = pack2(r0, r0), rb = pack2(r1, r1);
#pragma unroll
        for (int p = 0; p < 8; p++) {
            acc[p]     = fma2(ra, v[p],     acc[p]);
            acc[p + 8] = fma2(rb, v[p + 8], acc[p + 8]);
        }
    }

    // Flush: each (b, out) owned by exactly one thread in this block;
    // duplication only across the 64 i-tile blocks -> global reduction.
    float* dst = &g_preact[(size_t)b * OUT + out0];
#pragma unroll
    for (int p = 0; p < 16; p++) {
        float a0, a1; unpack2(acc[p], a0, a1);
        atomicAdd(dst + 2*p,     a0);
        atomicAdd(dst + 2*p + 1, a1);
    }
}

// ---------------------------------------------------------------- squash
__global__ void k_squash(const float* __restrict__ bias, float* __restrict__ out) {
    const int b = blockIdx.x;
    const int t = threadIdx.x;

    float p = g_preact[b * OUT + t] + bias[t];
    float sq = p * p;
#pragma unroll
    for (int d = 1; d < OA; d <<= 1)
        sq += __shfl_xor_sync(0xFFFFFFFFu, sq, d);   // sum over 16-lane group
    float nrm = sqrtf(sq);
    float scale = nrm / (1.0f + sq);
    float a = p * scale;

    out[b * OUT + t] = a;
    g_S[b * OUT + t] += a;
    g_preact[b * OUT + t] = 0.0f;
}

// ---------------------------------------------------------------- launch
extern "C" void kernel_launch(void* const* d_in, const int* in_sizes, int n_in,
                              void* d_out, int out_size) {
    const float* x    = (const float*)d_in[0];   // [64, 2048, 8]
    const float* W    = (const float*)d_in[1];   // [2048, 8, 512]
    const float* bias = (const float*)d_in[2];   // [32, 16]
    float* out = (float*)d_out;                  // [64, 32, 16]

    dim3 grid(NI / I_TILE, NB / 32);

    k_zero<<<64, 512>>>();
    k_route<true><<<grid, NTHR>>>(x, W);
    k_squash<<<NB, 512>>>(bias, out);
    k_route<false><<<grid, NTHR>>>(x, W);
    k_squash<<<NB, 512>>>(bias, out);
    k_route<false><<<grid, NTHR>>>(x, W);
    k_squash<<<NB, 512>>>(bias, out);
}

// round 4
// speedup vs baseline: 1.4947x; 1.4947x over previous
#include <cuda_runtime.h>
#include <cuda_fp16.h>
#include <math.h>

#define NB    64
#define NI    2048
#define KA    8
#define NO    32
#define OA    16
#define OUT   512

__device__ float g_S[NB * OUT];        // cumulative sum of activations
__device__ float g_preact[NB * OUT];
// votes fp16, SoA-chunked: uint2 (4 halves = atoms 4c..4c+3 of capsule j=lane)
// index: ((b*NI + i)*4 + c)*32 + lane          -> 128 MB
__device__ uint2 g_votes[(size_t)NB * NI * 4 * 32];

typedef unsigned long long u64;

// ---- f32x2 helpers ----
__device__ __forceinline__ u64 fma2(u64 a, u64 b, u64 c) {
    u64 d; asm("fma.rn.f32x2 %0, %1, %2, %3;" : "=l"(d) : "l"(a), "l"(b), "l"(c)); return d;
}
__device__ __forceinline__ u64 pack2(float lo, float hi) {
    u64 d; asm("mov.b64 %0, {%1, %2};" : "=l"(d) : "f"(lo), "f"(hi)); return d;
}
__device__ __forceinline__ void unpack2(u64 v, float& lo, float& hi) {
    asm("mov.b64 {%0, %1}, %2;" : "=f"(lo), "=f"(hi) : "l"(v));
}
__device__ __forceinline__ void cp16(void* smem_dst, const void* gsrc) {
    unsigned s = (unsigned)__cvta_generic_to_shared(smem_dst);
    asm volatile("cp.async.cg.shared.global [%0], [%1], 16;" :: "r"(s), "l"(gsrc));
}
__device__ __forceinline__ int swz(int b) { return b ^ ((b >> 3) & 0x70); }

// ---------------------------------------------------------------- zero
__global__ void k_zero() {
    int t = blockIdx.x * blockDim.x + threadIdx.x;
    if (t < NB * OUT) { g_S[t] = 0.0f; g_preact[t] = 0.0f; }
}

// ---------------------------------------------------------------- gen + pass0
// grid = (NI/32=64, NB/32=2), block 256 (8 warps). lane = j; warp owns 4 b.
// W[i] staged in smem (cp.async dbl buffer). Computes votes, stores them as
// fp16 (coalesced uint2 chunks), and accumulates pass-0 preact (route = 1/33).
#define ITA 32
__global__ void __launch_bounds__(256, 1)
k_gen(const float* __restrict__ x, const float* __restrict__ W) {
    __shared__ char ws[2 * KA * OUT * 4];     // 32 KB

    const int tid  = threadIdx.x;
    const int w    = tid >> 5;
    const int lane = tid & 31;
    const int it0  = blockIdx.x * ITA;
    const int b0   = blockIdx.y * 32 + w * 4;

    {   // prefetch W[it0..] first tile (16 KB)
        const float4* g = (const float4*)(W + (size_t)it0 * KA * OUT);
#pragma unroll
        for (int r = 0; r < 4; r++) { int f4 = tid + 256 * r; cp16(ws + swz(f4 * 16), &g[f4]); }
        asm volatile("cp.async.commit_group;" ::: "memory");
    }

    u64 acc[4][8];
#pragma unroll
    for (int bq = 0; bq < 4; bq++)
#pragma unroll
        for (int p = 0; p < 8; p++) acc[bq][p] = 0ull;
    const u64 c33 = pack2(1.0f / 33.0f, 1.0f / 33.0f);

    for (int ii = 0; ii < ITA; ii++) {
        asm volatile("cp.async.wait_group 0;" ::: "memory");
        __syncthreads();

        if (ii + 1 < ITA) {
            const float4* g = (const float4*)(W + (size_t)(it0 + ii + 1) * KA * OUT);
            char* dst = ws + ((ii + 1) & 1) * (KA * OUT * 4);
#pragma unroll
            for (int r = 0; r < 4; r++) { int f4 = tid + 256 * r; cp16(dst + swz(f4 * 16), &g[f4]); }
            asm volatile("cp.async.commit_group;" ::: "memory");
        }

        const char* Wc = ws + (ii & 1) * (KA * OUT * 4);
        const int i = it0 + ii;

        float xk[4][KA];
#pragma unroll
        for (int bq = 0; bq < 4; bq++) {
            const float4* xp = (const float4*)&x[((size_t)(b0 + bq) * NI + i) * KA];
            float4 x0 = __ldg(xp), x1 = __ldg(xp + 1);
            xk[bq][0]=x0.x; xk[bq][1]=x0.y; xk[bq][2]=x0.z; xk[bq][3]=x0.w;
            xk[bq][4]=x1.x; xk[bq][5]=x1.y; xk[bq][6]=x1.z; xk[bq][7]=x1.w;
        }

        u64 v[4][8];
#pragma unroll
        for (int bq = 0; bq < 4; bq++)
#pragma unroll
            for (int p = 0; p < 8; p++) v[bq][p] = 0ull;

#pragma unroll
        for (int k = 0; k < KA; k++) {
            u64 xb[4];
#pragma unroll
            for (int bq = 0; bq < 4; bq++) xb[bq] = pack2(xk[bq][k], xk[bq][k]);
#pragma unroll
            for (int q = 0; q < 4; q++) {
                ulonglong2 wv = *(const ulonglong2*)(Wc + swz(k * 2048 + lane * 64 + q * 16));
#pragma unroll
                for (int bq = 0; bq < 4; bq++) {
                    v[bq][2*q]   = fma2(xb[bq], wv.x, v[bq][2*q]);
                    v[bq][2*q+1] = fma2(xb[bq], wv.y, v[bq][2*q+1]);
                }
            }
        }

        // accumulate pass0 + convert/store fp16 votes (coalesced STG.64)
#pragma unroll
        for (int bq = 0; bq < 4; bq++) {
            __half2 h[8];
#pragma unroll
            for (int p = 0; p < 8; p++) {
                acc[bq][p] = fma2(c33, v[bq][p], acc[bq][p]);
                float f0, f1; unpack2(v[bq][p], f0, f1);
                h[p] = __floats2half2_rn(f0, f1);
            }
            uint2* dst = &g_votes[(((size_t)(b0 + bq) * NI + i) * 4) * 32 + lane];
#pragma unroll
            for (int c = 0; c < 4; c++) {
                uint2 val = make_uint2(*(unsigned*)&h[2*c], *(unsigned*)&h[2*c+1]);
                dst[c * 32] = val;
            }
        }
    }

#pragma unroll
    for (int bq = 0; bq < 4; bq++) {
        float* dst = &g_preact[(size_t)(b0 + bq) * OUT + lane * OA];
#pragma unroll
        for (int p = 0; p < 8; p++) {
            float a0, a1; unpack2(acc[bq][p], a0, a1);
            atomicAdd(dst + 2*p, a0);
            atomicAdd(dst + 2*p + 1, a1);
        }
    }
}

// ---------------------------------------------------------------- route pass (1,2)
// grid = (8, 64): warp = (b = by, i-chunk = bx*8+w of 32 i), lane = j.
// Streams fp16 votes, logit = v.S, leaky softmax over 32 lanes, acc in regs.
#define IW 32
__global__ void __launch_bounds__(256)
k_pass() {
    const int tid  = threadIdx.x;
    const int w    = tid >> 5;
    const int lane = tid & 31;
    const int b    = blockIdx.y;
    const int i0   = (blockIdx.x * 8 + w) * IW;

    // S[b, lane*16 .. +16) in 8 u64 regs
    u64 s[8];
    {
        const ulonglong2* sp = (const ulonglong2*)&g_S[(size_t)b * OUT + lane * OA];
#pragma unroll
        for (int q = 0; q < 4; q++) { ulonglong2 t = __ldg(sp + q); s[2*q] = t.x; s[2*q+1] = t.y; }
    }

    u64 acc[8];
#pragma unroll
    for (int p = 0; p < 8; p++) acc[p] = 0ull;

    const uint2* src = &g_votes[(((size_t)b * NI + i0) * 4) * 32 + lane];

#pragma unroll 4
    for (int m = 0; m < IW; m++) {
        uint2 u[4];
#pragma unroll
        for (int c = 0; c < 4; c++) u[c] = __ldg(src + (size_t)m * 128 + c * 32);

        u64 v[8];
#pragma unroll
        for (int c = 0; c < 4; c++) {
            float2 f0 = __half22float2(*(__half2*)&u[c].x);
            float2 f1 = __half22float2(*(__half2*)&u[c].y);
            v[2*c]   = pack2(f0.x, f0.y);
            v[2*c+1] = pack2(f1.x, f1.y);
        }

        u64 l2 = 0ull;
#pragma unroll
        for (int p = 0; p < 8; p++) l2 = fma2(v[p], s[p], l2);
        float a0, a1; unpack2(l2, a0, a1);
        float e = __expf(a0 + a1);

        float tot = e;
#pragma unroll
        for (int d = 16; d > 0; d >>= 1)
            tot += __shfl_xor_sync(0xFFFFFFFFu, tot, d);
        float r = __fdividef(e, 1.0f + tot);       // leaky softmax (leak logit 0)

        u64 r2 = pack2(r, r);
#pragma unroll
        for (int p = 0; p < 8; p++) acc[p] = fma2(r2, v[p], acc[p]);
    }

    float* dst = &g_preact[(size_t)b * OUT + lane * OA];
#pragma unroll
    for (int p = 0; p < 8; p++) {
        float a0, a1; unpack2(acc[p], a0, a1);
        atomicAdd(dst + 2*p, a0);
        atomicAdd(dst + 2*p + 1, a1);
    }
}

// ---------------------------------------------------------------- squash
__global__ void k_squash(const float* __restrict__ bias, float* __restrict__ out) {
    const int b = blockIdx.x;
    const int t = threadIdx.x;

    float p = g_preact[b * OUT + t] + bias[t];
    float sq = p * p;
#pragma unroll
    for (int d = 1; d < OA; d <<= 1)
        sq += __shfl_xor_sync(0xFFFFFFFFu, sq, d);
    float nrm = sqrtf(sq);
    float scale = nrm / (1.0f + sq);
    float a = p * scale;

    out[b * OUT + t] = a;
    g_S[b * OUT + t] += a;
    g_preact[b * OUT + t] = 0.0f;
}

// ---------------------------------------------------------------- launch
extern "C" void kernel_launch(void* const* d_in, const int* in_sizes, int n_in,
                              void* d_out, int out_size) {
    const float* x    = (const float*)d_in[0];
    const float* W    = (const float*)d_in[1];
    const float* bias = (const float*)d_in[2];
    float* out = (float*)d_out;

    k_zero<<<64, 512>>>();
    k_gen<<<dim3(NI / ITA, NB / 32), 256>>>(x, W);     // votes + pass 0
    k_squash<<<NB, 512>>>(bias, out);
    k_pass<<<dim3(8, NB), 256>>>();                    // pass 1
    k_squash<<<NB, 512>>>(bias, out);
    k_pass<<<dim3(8, NB), 256>>>();                    // pass 2
    k_squash<<<NB, 512>>>(bias, out);
}